// round 6
// baseline (speedup 1.0000x reference)
#include <cuda_runtime.h>
#include <math.h>

// S4 diagonal complex SSM scan, chunked 3-pass formulation.
// R6: 8-way state split (2 states = 1 f32x2 pair per thread) -> ~40-50 regs,
//     10 blocks/SM target. Transposed padded smem x tile [d][t] (stride 68)
//     -> one LDS.128 per 4 timesteps. pass3 output staged in smem, stored
//     cooperatively as float4. pass1 keeps k=4 step blocking.

#define LL 4096
#define DD 1024
#define NN 16
#define CC 64       // chunks
#define TT 64       // timesteps per chunk
#define DW 16       // d-channels per block (128 threads / 8 octs)
#define PAD 68      // padded row stride for smem tiles ([DW][PAD])

__device__ float g_S_re[CC * DD * NN];
__device__ float g_S_im[CC * DD * NN];

// ---------------- packed f32x2 helpers ----------------
struct f2 { unsigned long long v; };

__device__ __forceinline__ f2 f2pack(float lo, float hi) {
    f2 r; asm("mov.b64 %0, {%1, %2};" : "=l"(r.v) : "f"(lo), "f"(hi)); return r;
}
__device__ __forceinline__ void f2unpack(f2 a, float& lo, float& hi) {
    asm("mov.b64 {%0, %1}, %2;" : "=f"(lo), "=f"(hi) : "l"(a.v));
}
__device__ __forceinline__ f2 f2fma(f2 a, f2 b, f2 c) {
    f2 r; asm("fma.rn.f32x2 %0, %1, %2, %3;" : "=l"(r.v) : "l"(a.v), "l"(b.v), "l"(c.v)); return r;
}
__device__ __forceinline__ f2 f2mul(f2 a, f2 b) {
    f2 r; asm("mul.rn.f32x2 %0, %1, %2;" : "=l"(r.v) : "l"(a.v), "l"(b.v)); return r;
}
__device__ __forceinline__ f2 f2zero() { f2 r; r.v = 0ull; return r; }

__device__ __forceinline__ float softplus_f(float v) {
    return (v > 20.0f) ? v : log1pf(expf(v));
}

__device__ __forceinline__ void lam_dn(float dt, float ar, float ai,
                                       float& lre, float& lim) {
    float m = expf(dt * ar);
    float s, c;
    sincosf(dt * ai, &s, &c);
    lre = m * c;
    lim = m * s;
}

// cooperative coalesced load of this block's x tile, TRANSPOSED: xs_sm[d][t]
__device__ __forceinline__ void load_x_tile_T(float* xs_sm, const float* x,
                                              int c, int d0, int tid) {
    const float* xg = x + (size_t)c * TT * DD + d0;
    #pragma unroll
    for (int r = 0; r < 2; r++) {
        const int idx = tid + r * 128;     // 0..255 float4 slots
        const int t  = idx >> 2;           // 0..63
        const int dq = (idx & 3) * 4;      // 0,4,8,12
        float4 v = *(const float4*)&xg[t * DD + dq];
        xs_sm[(dq + 0) * PAD + t] = v.x;
        xs_sm[(dq + 1) * PAD + t] = v.y;
        xs_sm[(dq + 2) * PAD + t] = v.z;
        xs_sm[(dq + 3) * PAD + t] = v.w;
    }
}

// ---------------- pass 1: local chunk scans, k=4 step blocking --------------
__global__ void __launch_bounds__(128, 10)
s4_pass1(const float* __restrict__ x, const float* __restrict__ Delta,
         const float* __restrict__ A_re, const float* __restrict__ A_im,
         const float* __restrict__ B_re, const float* __restrict__ B_im) {
    __shared__ float xs_sm[DW * PAD];
    const int tid = threadIdx.x;
    const int dl  = tid >> 3;          // 0..15
    const int o   = tid & 7;           // oct -> 2 states
    const int d   = blockIdx.x * DW + dl;
    const int nb  = o * 2;
    const int c   = blockIdx.y;

    load_x_tile_T(xs_sm, x, c, blockIdx.x * DW, tid);

    const float dt = softplus_f(Delta[d]);
    const float2 ar2 = *(const float2*)&A_re[d * NN + nb];
    const float2 ai2 = *(const float2*)&A_im[d * NN + nb];
    const float2 br2 = *(const float2*)&B_re[d * NN + nb];
    const float2 bi2 = *(const float2*)&B_im[d * NN + nb];
    const float arr[2] = {ar2.x, ar2.y};
    const float aii[2] = {ai2.x, ai2.y};
    const float brr[2] = {br2.x, br2.y};
    const float bii[2] = {bi2.x, bi2.y};

    float l4r[2], l4i[2];
    float c0r[2], c0i[2], c1r[2], c1i[2], c2r[2], c2i[2], c3r[2], c3i[2];
    #pragma unroll
    for (int k = 0; k < 2; k++) {
        float lr, li;
        lam_dn(dt, arr[k], aii[k], lr, li);
        c0r[k] = dt * brr[k];
        c0i[k] = dt * bii[k];
        c1r[k] = lr * c0r[k] - li * c0i[k];
        c1i[k] = lr * c0i[k] + li * c0r[k];
        c2r[k] = lr * c1r[k] - li * c1i[k];
        c2i[k] = lr * c1i[k] + li * c1r[k];
        c3r[k] = lr * c2r[k] - li * c2i[k];
        c3i[k] = lr * c2i[k] + li * c2r[k];
        const float l2r = lr * lr - li * li;
        const float l2i = 2.0f * lr * li;
        l4r[k] = l2r * l2r - l2i * l2i;
        l4i[k] = 2.0f * l2r * l2i;
    }

    const f2 L4re  = f2pack(l4r[0], l4r[1]);
    const f2 L4im  = f2pack(l4i[0], l4i[1]);
    const f2 nL4im = f2pack(-l4i[0], -l4i[1]);
    const f2 C0r = f2pack(c0r[0], c0r[1]), C0i = f2pack(c0i[0], c0i[1]);
    const f2 C1r = f2pack(c1r[0], c1r[1]), C1i = f2pack(c1i[0], c1i[1]);
    const f2 C2r = f2pack(c2r[0], c2r[1]), C2i = f2pack(c2i[0], c2i[1]);
    const f2 C3r = f2pack(c3r[0], c3r[1]), C3i = f2pack(c3i[0], c3i[1]);

    f2 hre = f2zero(), him = f2zero();

    __syncthreads();

    const float* xr = &xs_sm[dl * PAD];
    #pragma unroll 4
    for (int t = 0; t < TT; t += 4) {
        const float4 xv = *(const float4*)&xr[t];
        const f2 x1 = f2pack(xv.x, xv.x), x2 = f2pack(xv.y, xv.y);
        const f2 x3 = f2pack(xv.z, xv.z), x4 = f2pack(xv.w, xv.w);
        f2 tr = f2fma(C1r, x3, f2mul(C0r, x4));
        tr = f2fma(C2r, x2, tr);
        tr = f2fma(C3r, x1, tr);
        f2 ti = f2fma(C1i, x3, f2mul(C0i, x4));
        ti = f2fma(C2i, x2, ti);
        ti = f2fma(C3i, x1, ti);
        f2 nr = f2fma(L4re, hre, f2fma(nL4im, him, tr));
        f2 ni = f2fma(L4re, him, f2fma(L4im,  hre, ti));
        hre = nr; him = ni;
    }

    float r0, r1, i0, i1;
    f2unpack(hre, r0, r1);
    f2unpack(him, i0, i1);
    const int base = (c * DD + d) * NN + nb;
    *(float2*)&g_S_re[base] = make_float2(r0, r1);
    *(float2*)&g_S_im[base] = make_float2(i0, i1);
}

// ---------------- pass 2: cross-chunk scan (ends -> inits, in place) --------
__global__ void __launch_bounds__(128)
s4_pass2(const float* __restrict__ Delta,
         const float* __restrict__ A_re, const float* __restrict__ A_im) {
    const int i = blockIdx.x * blockDim.x + threadIdx.x;  // i = d*NN + n
    const int d = i >> 4;

    const float dt = softplus_f(Delta[d]);
    float lr, li;
    lam_dn(dt, A_re[i], A_im[i], lr, li);
    #pragma unroll
    for (int s = 0; s < 6; s++) {   // Lam^64
        float nr = lr * lr - li * li;
        li = 2.0f * lr * li;
        lr = nr;
    }

    float er[8], ei[8];
    #pragma unroll
    for (int u = 0; u < 8; u++) {
        const int idx = u * (DD * NN) + i;
        er[u] = g_S_re[idx];
        ei[u] = g_S_im[idx];
    }

    float hr = 0.0f, hi = 0.0f;
    #pragma unroll 1
    for (int cb = 0; cb < CC; cb += 8) {
        const bool more = (cb + 8) < CC;
        float er2[8], ei2[8];
        #pragma unroll
        for (int u = 0; u < 8; u++) {
            const int idx = (cb + 8 + u) * (DD * NN) + i;
            er2[u] = more ? g_S_re[idx] : 0.0f;
            ei2[u] = more ? g_S_im[idx] : 0.0f;
        }
        #pragma unroll
        for (int u = 0; u < 8; u++) {
            const int idx = (cb + u) * (DD * NN) + i;
            g_S_re[idx] = hr;
            g_S_im[idx] = hi;
            const float tr = lr * hr - li * hi + er[u];
            hi = lr * hi + li * hr + ei[u];
            hr = tr;
        }
        #pragma unroll
        for (int u = 0; u < 8; u++) { er[u] = er2[u]; ei[u] = ei2[u]; }
    }
}

// ---------------- pass 3: full scan with init state, emit output ------------
__global__ void __launch_bounds__(128, 10)
s4_pass3(const float* __restrict__ x, const float* __restrict__ Delta,
         const float* __restrict__ A_re, const float* __restrict__ A_im,
         const float* __restrict__ B_re, const float* __restrict__ B_im,
         const float* __restrict__ C_re, const float* __restrict__ C_im,
         const float* __restrict__ D_param, float* __restrict__ out) {
    __shared__ float xs_sm[DW * PAD];
    __shared__ float ys_sm[DW * PAD];
    const int tid = threadIdx.x;
    const int dl  = tid >> 3;
    const int o   = tid & 7;
    const int d   = blockIdx.x * DW + dl;
    const int nb  = o * 2;
    const int c   = blockIdx.y;

    load_x_tile_T(xs_sm, x, c, blockIdx.x * DW, tid);

    const float dt = softplus_f(Delta[d]);
    const float Dp = D_param[d];

    const float2 ar2 = *(const float2*)&A_re[d * NN + nb];
    const float2 ai2 = *(const float2*)&A_im[d * NN + nb];
    const float2 br2 = *(const float2*)&B_re[d * NN + nb];
    const float2 bi2 = *(const float2*)&B_im[d * NN + nb];
    const float2 cr2 = *(const float2*)&C_re[d * NN + nb];
    const float2 ci2 = *(const float2*)&C_im[d * NN + nb];
    const int base = (c * DD + d) * NN + nb;
    const float2 h0r2 = *(const float2*)&g_S_re[base];
    const float2 h0i2 = *(const float2*)&g_S_im[base];

    const float arr[2] = {ar2.x, ar2.y};
    const float aii[2] = {ai2.x, ai2.y};
    const float brr[2] = {br2.x, br2.y};
    const float bii[2] = {bi2.x, bi2.y};
    const float crr[2] = {cr2.x, cr2.y};
    const float cii[2] = {ci2.x, ci2.y};
    const float hrr[2] = {h0r2.x, h0r2.y};
    const float hii[2] = {h0i2.x, h0i2.y};

    // g = C (.) h: g' = Lam g + (C*dt*B) x, y = sum Re(g) over all n
    float lr[2], li[2], vr[2], vi[2], gr[2], gi[2];
    #pragma unroll
    for (int k = 0; k < 2; k++) {
        lam_dn(dt, arr[k], aii[k], lr[k], li[k]);
        const float br = dt * brr[k], bi = dt * bii[k];
        vr[k] = crr[k] * br - cii[k] * bi;
        vi[k] = crr[k] * bi + cii[k] * br;
        gr[k] = crr[k] * hrr[k] - cii[k] * hii[k];
        gi[k] = crr[k] * hii[k] + cii[k] * hrr[k];
    }

    const f2 lre  = f2pack(lr[0], lr[1]);
    const f2 lim  = f2pack(li[0], li[1]);
    const f2 nlim = f2pack(-li[0], -li[1]);
    const f2 wre  = f2pack(vr[0], vr[1]);
    const f2 wim  = f2pack(vi[0], vi[1]);
    f2 gre = f2pack(gr[0], gr[1]);
    f2 gim = f2pack(gi[0], gi[1]);

    __syncthreads();

    const float* xr = &xs_sm[dl * PAD];
    float* yw = &ys_sm[dl * PAD];

    #pragma unroll 1
    for (int tb = 0; tb < TT; tb += 8) {
        const float4 xa = *(const float4*)&xr[tb];
        const float4 xb = *(const float4*)&xr[tb + 4];
        const float xs[8] = {xa.x, xa.y, xa.z, xa.w, xb.x, xb.y, xb.z, xb.w};
        float ys[8];
        #pragma unroll
        for (int u = 0; u < 8; u++) {
            f2 x2 = f2pack(xs[u], xs[u]);
            f2 nr = f2fma(lre, gre, f2fma(nlim, gim, f2mul(wre, x2)));
            f2 ni = f2fma(lre, gim, f2fma(lim,  gre, f2mul(wim, x2)));
            gre = nr; gim = ni;
            float lo, hi;
            f2unpack(gre, lo, hi);
            ys[u] = lo + hi;
        }
        // reduce over 8 octs (adjacent lanes), batched
        #pragma unroll
        for (int u = 0; u < 8; u++)
            ys[u] += __shfl_xor_sync(0xFFFFFFFFu, ys[u], 1);
        #pragma unroll
        for (int u = 0; u < 8; u++)
            ys[u] += __shfl_xor_sync(0xFFFFFFFFu, ys[u], 2);
        #pragma unroll
        for (int u = 0; u < 8; u++)
            ys[u] += __shfl_xor_sync(0xFFFFFFFFu, ys[u], 4);
        if (o == 0) {
            #pragma unroll
            for (int u = 0; u < 8; u++)
                yw[tb + u] = ys[u] + Dp * xs[u];
        }
    }

    __syncthreads();

    // cooperative coalesced float4 store of the y tile
    float* og = out + (size_t)c * TT * DD + blockIdx.x * DW;
    #pragma unroll
    for (int r = 0; r < 2; r++) {
        const int idx = tid + r * 128;     // 0..255 float4 slots
        const int t  = idx >> 2;
        const int dq = (idx & 3) * 4;
        float4 v;
        v.x = ys_sm[(dq + 0) * PAD + t];
        v.y = ys_sm[(dq + 1) * PAD + t];
        v.z = ys_sm[(dq + 2) * PAD + t];
        v.w = ys_sm[(dq + 3) * PAD + t];
        *(float4*)&og[t * DD + dq] = v;
    }
}

extern "C" void kernel_launch(void* const* d_in, const int* in_sizes, int n_in,
                              void* d_out, int out_size) {
    const float* x     = (const float*)d_in[0];
    const float* Delta = (const float*)d_in[1];
    const float* A_re  = (const float*)d_in[2];
    const float* A_im  = (const float*)d_in[3];
    const float* B_re  = (const float*)d_in[4];
    const float* B_im  = (const float*)d_in[5];
    const float* C_re  = (const float*)d_in[6];
    const float* C_im  = (const float*)d_in[7];
    const float* Dp    = (const float*)d_in[8];
    float* out = (float*)d_out;

    dim3 blk(128);
    dim3 g13(DD / DW, CC);
    s4_pass1<<<g13, blk>>>(x, Delta, A_re, A_im, B_re, B_im);
    s4_pass2<<<(DD * NN) / 128, blk>>>(Delta, A_re, A_im);
    s4_pass3<<<g13, blk>>>(x, Delta, A_re, A_im, B_re, B_im, C_re, C_im, Dp, out);
}